// round 2
// baseline (speedup 1.0000x reference)
#include <cuda_runtime.h>
#include <cstdint>

// SPPoolMean: per (B*C=512) row of N=65536 pixels, scatter-mean over 512
// labels, gather mean back to every pixel.
//
// Labels arrive as int32 (harness has no int64 path; JAX default is 32-bit).
//
// One CTA per row. SMEM: u16 label cache (128KB) + packed u64 histogram (4KB)
// + decoded means (2KB). One packed 64-bit SMEM atomic per element:
//   addend = (1<<44) | (uint)( round(v * 2^20) + 2^24 )
// count lives in bits [44:64), biased Q20 fixed-point sum in bits [0:44).

#define NBINS   512
#define NPIX    65536           // 256*256
#define THREADS 1024
#define ITERS   (NPIX / (THREADS * 4))   // 16

#define SMEM_LAB_BYTES  (NPIX * 2)       // 131072
#define SMEM_HIST_BYTES (NBINS * 8)      // 4096
#define SMEM_MEAN_BYTES (NBINS * 4)      // 2048
#define SMEM_TOTAL (SMEM_LAB_BYTES + SMEM_HIST_BYTES + SMEM_MEAN_BYTES)

__device__ __forceinline__ unsigned long long pack_val(float v) {
    // Q20 fixed point, biased by 2^24 so every addend is non-negative.
    int q = __float2int_rn(v * 1048576.0f);          // |v| < ~127 safe
    return (1ull << 44) + (unsigned long long)(unsigned int)(q + (1 << 24));
}

extern "C" __global__ void __launch_bounds__(THREADS, 1)
sppool_kernel(const float* __restrict__ src,
              const int* __restrict__ lab,
              float* __restrict__ out)
{
    extern __shared__ unsigned char smem_raw[];
    unsigned short* slab = reinterpret_cast<unsigned short*>(smem_raw);
    unsigned long long* hist =
        reinterpret_cast<unsigned long long*>(smem_raw + SMEM_LAB_BYTES);
    float* smean =
        reinterpret_cast<float*>(smem_raw + SMEM_LAB_BYTES + SMEM_HIST_BYTES);

    const int row = blockIdx.x;
    const int tid = threadIdx.x;

    const float* s = src + (size_t)row * NPIX;
    const int*   l = lab + (size_t)row * NPIX;
    float*       o = out + (size_t)row * NPIX;

    // zero histogram (512 x u64 = 256 x ulonglong2)
    if (tid < NBINS / 2) {
        reinterpret_cast<ulonglong2*>(hist)[tid] = make_ulonglong2(0ull, 0ull);
    }
    __syncthreads();

    // Phase 1: stream row, cache labels as u16, packed atomic histogram.
#pragma unroll
    for (int k = 0; k < ITERS; k++) {
        const int i = k * (THREADS * 4) + tid * 4;

        float4 v = *reinterpret_cast<const float4*>(s + i);
        int4   li = *reinterpret_cast<const int4*>(l + i);

        int a = li.x & (NBINS - 1);
        int b = li.y & (NBINS - 1);
        int c = li.z & (NBINS - 1);
        int d = li.w & (NBINS - 1);

        ushort4 u = make_ushort4((unsigned short)a, (unsigned short)b,
                                 (unsigned short)c, (unsigned short)d);
        *reinterpret_cast<ushort4*>(slab + i) = u;

        atomicAdd(&hist[a], pack_val(v.x));
        atomicAdd(&hist[b], pack_val(v.y));
        atomicAdd(&hist[c], pack_val(v.z));
        atomicAdd(&hist[d], pack_val(v.w));
    }
    __syncthreads();

    // Phase 2: decode per-bin mean.
    if (tid < NBINS) {
        unsigned long long w = hist[tid];
        long long count = (long long)(w >> 44);
        long long low   = (long long)(w & ((1ull << 44) - 1ull));
        long long sumq  = low - (count << 24);
        // count==0 bins are never gathered; garbage there is harmless.
        smean[tid] = (float)((double)sumq * (1.0 / 1048576.0) /
                             (double)(count | (count == 0)));
    }
    __syncthreads();

    // Phase 3: gather from SMEM label cache, write float4.
#pragma unroll
    for (int k = 0; k < ITERS; k++) {
        const int i = k * (THREADS * 4) + tid * 4;
        ushort4 u = *reinterpret_cast<const ushort4*>(slab + i);
        float4 r;
        r.x = smean[u.x];
        r.y = smean[u.y];
        r.z = smean[u.z];
        r.w = smean[u.w];
        *reinterpret_cast<float4*>(o + i) = r;
    }
}

extern "C" void kernel_launch(void* const* d_in, const int* in_sizes, int n_in,
                              void* d_out, int out_size)
{
    const float* src = (const float*)d_in[0];
    const int*   lab = (const int*)d_in[1];
    float*       out = (float*)d_out;

    const int rows = in_sizes[0] / NPIX;   // 512

    static bool attr_set = false;
    if (!attr_set) {
        cudaFuncSetAttribute(sppool_kernel,
                             cudaFuncAttributeMaxDynamicSharedMemorySize,
                             SMEM_TOTAL);
        attr_set = true;
    }

    sppool_kernel<<<rows, THREADS, SMEM_TOTAL>>>(src, lab, out);
}